// round 8
// baseline (speedup 1.0000x reference)
#include <cuda_runtime.h>
#include <cuda_bf16.h>
#include <cstdint>

// ---------------- problem constants ----------------
#define BSZ 2
#define SEQ 2048
#define DIM 1024
#define NST 16
#define TOK (BSZ * SEQ)      // 4096 tokens
#define KPHY 2048            // physical K: [hi | lo]
#define NPAD 1152            // 1056 cols (dt 1024 + B 16 + C 16) padded
#define CH 16                // scan chunks
#define CL 128               // chunk length = SEQ/CH

// ---------------- scratch (device globals; no allocs allowed) ----------------
__device__ __nv_bfloat16 g_Abig[(size_t)TOK * KPHY];   // [t][k] hi|lo  16 MB
__device__ __nv_bfloat16 g_Bbig[(size_t)NPAD * KPHY];  // [n][k] hi|lo  4.5 MB
__device__ float g_xn [(size_t)TOK * DIM];             // layernormed x, [t][d]
__device__ float g_xnT[(size_t)DIM * TOK];             // xn transposed [d][t]
__device__ float g_dtT[(size_t)DIM * TOK];             // softplus(dt), [d][t]
__device__ float g_BT [(size_t)NST * TOK];             // B_in^T [n][t]
__device__ float g_CT [(size_t)NST * TOK];             // C_in^T [n][t]
__device__ float g_H [(size_t)BSZ * DIM * NST * CH];   // per-chunk zero-init final h
__device__ float g_P [(size_t)BSZ * DIM * NST * CH];   // per-chunk total decay
__device__ float g_h0[(size_t)BSZ * DIM * NST * CH];   // per-chunk initial state

// ---------------- helpers ----------------
__device__ __forceinline__ uint32_t smem_u32(const void* p) {
    uint32_t a;
    asm("{ .reg .u64 t; cvta.to.shared.u64 t, %1; cvt.u32.u64 %0, t; }"
        : "=r"(a) : "l"(p));
    return a;
}
__device__ __forceinline__ void cp_async16(uint32_t s, const void* g) {
    asm volatile("cp.async.cg.shared.global [%0], [%1], 16;"
                 :: "r"(s), "l"(__cvta_generic_to_global(g)) : "memory");
}
__device__ __forceinline__ void cp_commit() {
    asm volatile("cp.async.commit_group;" ::: "memory");
}
template <int N>
__device__ __forceinline__ void cp_wait() {
    asm volatile("cp.async.wait_group %0;" :: "n"(N) : "memory");
}
__device__ __forceinline__ void ldsm_x4(uint32_t& r0, uint32_t& r1,
                                        uint32_t& r2, uint32_t& r3, uint32_t a) {
    asm volatile("ldmatrix.sync.aligned.m8n8.x4.shared.b16 {%0,%1,%2,%3}, [%4];"
                 : "=r"(r0), "=r"(r1), "=r"(r2), "=r"(r3) : "r"(a));
}
__device__ __forceinline__ void mma16816(float* c, const uint32_t* a,
                                         const uint32_t* b) {
    asm volatile(
        "mma.sync.aligned.m16n8k16.row.col.f32.bf16.bf16.f32 "
        "{%0,%1,%2,%3}, {%4,%5,%6,%7}, {%8,%9}, {%0,%1,%2,%3};"
        : "+f"(c[0]), "+f"(c[1]), "+f"(c[2]), "+f"(c[3])
        : "r"(a[0]), "r"(a[1]), "r"(a[2]), "r"(a[3]), "r"(b[0]), "r"(b[1]));
}

// ============================================================
// Kernel 1: LayerNorm + bf16 hi/lo split pack into A = [hi | lo]
// ============================================================
__global__ void __launch_bounds__(256) ln_kernel(const float* __restrict__ x,
                                                 const float* __restrict__ gamma,
                                                 const float* __restrict__ beta) {
    const int t = blockIdx.x;
    const int tid = threadIdx.x;
    float4 v = ((const float4*)(x + (size_t)t * DIM))[tid];
    float s  = v.x + v.y + v.z + v.w;
    float ss = v.x * v.x + v.y * v.y + v.z * v.z + v.w * v.w;
#pragma unroll
    for (int o = 16; o; o >>= 1) {
        s  += __shfl_xor_sync(0xffffffffu, s,  o);
        ss += __shfl_xor_sync(0xffffffffu, ss, o);
    }
    __shared__ float red[16];
    const int w = tid >> 5, lane = tid & 31;
    if (lane == 0) { red[w] = s; red[8 + w] = ss; }
    __syncthreads();
    if (tid == 0) {
        float a = 0.f, b2 = 0.f;
#pragma unroll
        for (int i = 0; i < 8; ++i) { a += red[i]; b2 += red[8 + i]; }
        red[0] = a; red[8] = b2;
    }
    __syncthreads();
    const float mu  = red[0] * (1.f / DIM);
    const float var = red[8] * (1.f / DIM) - mu * mu;
    const float rs  = rsqrtf(var + 1e-5f);
    float4 g  = ((const float4*)gamma)[tid];
    float4 bb = ((const float4*)beta)[tid];
    float4 xn;
    xn.x = (v.x - mu) * rs * g.x + bb.x;
    xn.y = (v.y - mu) * rs * g.y + bb.y;
    xn.z = (v.z - mu) * rs * g.z + bb.z;
    xn.w = (v.w - mu) * rs * g.w + bb.w;
    ((float4*)(g_xn + (size_t)t * DIM))[tid] = xn;

    __nv_bfloat16 h0 = __float2bfloat16(xn.x);
    __nv_bfloat16 h1 = __float2bfloat16(xn.y);
    __nv_bfloat16 h2 = __float2bfloat16(xn.z);
    __nv_bfloat16 h3 = __float2bfloat16(xn.w);
    __nv_bfloat16 l0 = __float2bfloat16(xn.x - __bfloat162float(h0));
    __nv_bfloat16 l1 = __float2bfloat16(xn.y - __bfloat162float(h1));
    __nv_bfloat16 l2 = __float2bfloat16(xn.z - __bfloat162float(h2));
    __nv_bfloat16 l3 = __float2bfloat16(xn.w - __bfloat162float(h3));

    __nv_bfloat16* base = g_Abig + (size_t)t * KPHY + tid * 4;
    ((__nv_bfloat162*)(base))[0]        = __halves2bfloat162(h0, h1);
    ((__nv_bfloat162*)(base))[1]        = __halves2bfloat162(h2, h3);
    ((__nv_bfloat162*)(base + 1024))[0] = __halves2bfloat162(l0, l1);
    ((__nv_bfloat162*)(base + 1024))[1] = __halves2bfloat162(l2, l3);
}

// ============================================================
// Kernel 2: pack weights B = [hi | lo]
// ============================================================
__global__ void __launch_bounds__(256) wpack_kernel(const float* __restrict__ W_dt,
                                                    const float* __restrict__ W_B,
                                                    const float* __restrict__ W_C) {
    const int r = blockIdx.x;
    const float* wrow = nullptr;
    if (r < 1024)       wrow = W_dt + (size_t)r * DIM;
    else if (r < 1040)  wrow = W_B  + (size_t)(r - 1024) * DIM;
    else if (r < 1056)  wrow = W_C  + (size_t)(r - 1040) * DIM;
    for (int k = threadIdx.x; k < KPHY; k += 256) {
        float wv = 0.f;
        const int kk  = k & 1023;
        const int blk = k >> 10;
        if (wrow) wv = wrow[kk];
        __nv_bfloat16 hi = __float2bfloat16(wv);
        __nv_bfloat16 outv = blk
            ? __float2bfloat16(wv - __bfloat162float(hi)) : hi;
        g_Bbig[(size_t)r * KPHY + k] = outv;
    }
}

// ============================================================
// Kernel 2b: xn transpose  [t][d] -> [d][t]
// ============================================================
__global__ void __launch_bounds__(256) xpose_kernel() {
    __shared__ float s[32][33];
    const int t0 = blockIdx.x * 32;
    const int d0 = blockIdx.y * 32;
    const int tx = threadIdx.x & 31;
    const int ty = threadIdx.x >> 5;
#pragma unroll
    for (int i = 0; i < 4; ++i)
        s[ty + i * 8][tx] = g_xn[(size_t)(t0 + ty + i * 8) * DIM + d0 + tx];
    __syncthreads();
#pragma unroll
    for (int i = 0; i < 4; ++i)
        g_xnT[(size_t)(d0 + ty + i * 8) * TOK + t0 + tx] = s[tx][ty + i * 8];
}

// ============================================================
// Kernel 3: bf16 mma.sync GEMM, CTA tile 256x128, BK=32,
// 4-stage cp.async pipeline, one sync per chunk.
// logical K=3072 via 96-chunk remap over physical [hi|lo] storage.
// warp tile 64x64 (4 warps along M, 2 along N).
// ============================================================
#define BK 32
#define SROW 40                  // padded smem row stride in bf16 elems (80 B)
#define A_STAGE 20480            // 256 rows * 80 B
#define B_STAGE 10240            // 128 rows * 80 B
#define STAGE_BYTES (A_STAGE + B_STAGE)   // 30720
#define GEMM_SMEM (4 * STAGE_BYTES)       // 122880
#define TBP 260                  // transpose buffer pitch (words)

__global__ void __launch_bounds__(256) gemm_kernel(const float* __restrict__ b_dt) {
    extern __shared__ char smem_raw[];

    const int tid  = threadIdx.x;
    const int wid  = tid >> 5;
    const int lane = tid & 31;
    const int mt = blockIdx.x;    // 0..15 (256-token tiles)
    const int nt = blockIdx.y;    // 0..8
    const int warp_m = wid & 3;
    const int warp_n = wid >> 2;
    const int m0 = warp_m * 64;
    const int n0 = warp_n * 64;

    const __nv_bfloat16* Ag = g_Abig + (size_t)mt * 256 * KPHY;
    const __nv_bfloat16* Bg = g_Bbig + (size_t)nt * 128 * KPHY;

    const uint32_t sbase = smem_u32(smem_raw);

    // 96 logical chunks of 32: pass0 hi*hi, pass1 hi*lo, pass2 lo*hi
    auto load_tile = [&](int c, int stage) {
        const int pass = c >> 5;
        const int cc   = c & 31;
        const int ak0  = (pass == 2 ? 1024 : 0) + cc * 32;
        const int bk0  = (pass == 1 ? 1024 : 0) + cc * 32;
        const uint32_t sa = sbase + (uint32_t)stage * STAGE_BYTES;
        const uint32_t sb = sa + A_STAGE;
        // A: 256 rows x 64B = 1024 chunks of 16B; 4 per thread
#pragma unroll
        for (int r = 0; r < 4; ++r) {
            const int id  = tid * 4 + r;        // 0..1023
            const int row = id >> 2;
            const int ch  = id & 3;
            const uint32_t soff = (uint32_t)(row * SROW + ch * 8) * 2;
            cp_async16(sa + soff, Ag + (size_t)row * KPHY + ak0 + ch * 8);
        }
        // B: 128 rows x 64B = 512 chunks; 2 per thread
#pragma unroll
        for (int r = 0; r < 2; ++r) {
            const int id  = tid * 2 + r;        // 0..511
            const int row = id >> 2;
            const int ch  = id & 3;
            const uint32_t soff = (uint32_t)(row * SROW + ch * 8) * 2;
            cp_async16(sb + soff, Bg + (size_t)row * KPHY + bk0 + ch * 8);
        }
        cp_commit();
    };

    float acc[4][8][4];
#pragma unroll
    for (int mf = 0; mf < 4; ++mf)
#pragma unroll
        for (int nf = 0; nf < 8; ++nf)
#pragma unroll
            for (int i = 0; i < 4; ++i) acc[mf][nf][i] = 0.f;

    load_tile(0, 0);
    load_tile(1, 1);
    load_tile(2, 2);

    for (int c = 0; c < 96; ++c) {
        const int stage = c & 3;
        if (c < 94)       cp_wait<2>();
        else if (c == 94) cp_wait<1>();
        else              cp_wait<0>();
        __syncthreads();
        if (c + 3 < 96) load_tile(c + 3, (c + 3) & 3);

        const uint32_t sa = sbase + (uint32_t)stage * STAGE_BYTES;
        const uint32_t sb = sa + A_STAGE;
#pragma unroll
        for (int kk = 0; kk < BK; kk += 16) {
            uint32_t a[4][4];
#pragma unroll
            for (int mf = 0; mf < 4; ++mf) {
                uint32_t addr = sa +
                    (uint32_t)((m0 + mf * 16 + (lane & 15)) * SROW +
                               kk + ((lane >> 4) << 3)) * 2;
                ldsm_x4(a[mf][0], a[mf][1], a[mf][2], a[mf][3], addr);
            }
            uint32_t b[8][2];
#pragma unroll
            for (int g = 0; g < 4; ++g) {
                const int nrow = n0 + g * 16 + ((lane >> 4) << 3) + (lane & 7);
                const int kcol = kk + (((lane >> 3) & 1) << 3);
                uint32_t addr = sb + (uint32_t)(nrow * SROW + kcol) * 2;
                uint32_t r0, r1, r2, r3;
                ldsm_x4(r0, r1, r2, r3, addr);
                b[g * 2][0]     = r0; b[g * 2][1]     = r1;
                b[g * 2 + 1][0] = r2; b[g * 2 + 1][1] = r3;
            }
#pragma unroll
            for (int mf = 0; mf < 4; ++mf)
#pragma unroll
                for (int nf = 0; nf < 8; ++nf)
                    mma16816(acc[mf][nf], a[mf], b[nf]);
        }
    }
    __syncthreads();

    // ---------------- epilogue ----------------
    // tb[col 0..63][tok 0..255], pitch TBP=260 words.
    // Write side: within a warp, bank = 8*(lane&3) + (lane>>2) -> conflict-free.
    // Read side: lane = token -> conflict-free, coalesced GMEM.
    float* tb = (float*)smem_raw;
    const int trow  = lane >> 2;
    const int cpair = (lane & 3) * 2;

#pragma unroll 1
    for (int h = 0; h < 2; ++h) {
        __syncthreads();
        if (warp_n == h) {
#pragma unroll
            for (int mf = 0; mf < 4; ++mf)
#pragma unroll
                for (int nf = 0; nf < 8; ++nf)
#pragma unroll
                    for (int i = 0; i < 4; ++i) {
                        const int tok_l = m0 + mf * 16 + trow + 8 * (i >> 1);
                        const int col_l = nf * 8 + cpair + (i & 1);
                        tb[col_l * TBP + tok_l] = acc[mf][nf][i];
                    }
        }
        __syncthreads();
        // store: warp w covers cols w*8..w*8+7; lanes over tokens
        if (nt < 8) {
#pragma unroll 1
            for (int ccx = 0; ccx < 8; ++ccx) {
                const int col = wid * 8 + ccx;
                const int dd = nt * 128 + h * 64 + col;
                const float bias = b_dt[dd];
                float* dst = g_dtT + (size_t)dd * TOK + mt * 256;
#pragma unroll
                for (int q = 0; q < 8; ++q) {
                    const int tl = q * 32 + lane;
                    float u = tb[col * TBP + tl] + bias;
                    dst[tl] = (u > 20.f) ? u : log1pf(expf(u));
                }
            }
        } else {
#pragma unroll 1
            for (int ccx = 0; ccx < 8; ++ccx) {
                const int col = wid * 8 + ccx;
                const int cc = h * 64 + col;
                if (cc < 32) {
                    float* dst = (cc < 16 ? g_BT + (size_t)cc * TOK
                                          : g_CT + (size_t)(cc - 16) * TOK) + mt * 256;
#pragma unroll
                    for (int q = 0; q < 8; ++q) {
                        const int tl = q * 32 + lane;
                        dst[tl] = tb[col * TBP + tl];
                    }
                }
            }
        }
    }
}

// ============================================================
// Kernel 4a: scan pass A — per-chunk zero-init final state H + decay P.
// ============================================================
__global__ void __launch_bounds__(256, 1) scanA_kernel(const float* __restrict__ A_log) {
    __shared__ float s_B[CL * 17];
    const int bx  = blockIdx.x;
    const int ch  = bx & (CH - 1);
    const int rest = bx >> 4;
    const int b   = rest >> 6;
    const int d0  = (rest & 63) << 4;
    const int tid = threadIdx.x;
    const int w   = tid >> 5;
    const int lane = tid & 31;
    const int half = lane >> 4;
    const int n    = lane & 15;
    const int d    = d0 + 2 * w + half;

    const size_t off = (size_t)b * SEQ + ch * CL;
#pragma unroll
    for (int q = 0; q < (CL * NST) / 256; ++q) {
        const int idx = q * 256 + tid;
        const int t  = idx & (CL - 1);
        const int nn = idx >> 7;
        s_B[t * 17 + nn] = g_BT[(size_t)nn * TOK + off + t];
    }
    __syncthreads();

    const float a_coef = -expf(A_log[d * NST + n]) * 1.44269504088896341f;
    const float* dtp = g_dtT + (size_t)d * TOK + off;
    const float* xnp = g_xnT + (size_t)d * TOK + off;

    float h = 0.f, S = 0.f;
#pragma unroll 1
    for (int l = 0; l < CL; l += 8) {
        const float4 dt0 = *(const float4*)(dtp + l);
        const float4 dt1 = *(const float4*)(dtp + l + 4);
        const float4 x0  = *(const float4*)(xnp + l);
        const float4 x1  = *(const float4*)(xnp + l + 4);
#define ASTEP(j, dtv, xv)                                   \
        {                                                   \
            const float Bv = s_B[(l + j) * 17 + n];         \
            const float a_ = exp2f((dtv) * a_coef);         \
            h = fmaf(a_, h, (dtv) * Bv * (xv));             \
            S += (dtv);                                     \
        }
        ASTEP(0, dt0.x, x0.x) ASTEP(1, dt0.y, x0.y)
        ASTEP(2, dt0.z, x0.z) ASTEP(3, dt0.w, x0.w)
        ASTEP(4, dt1.x, x1.x) ASTEP(5, dt1.y, x1.y)
        ASTEP(6, dt1.z, x1.z) ASTEP(7, dt1.w, x1.w)
#undef ASTEP
    }
    const size_t idx = (((size_t)b * DIM + d) * NST + n) * CH + ch;
    g_H[idx] = h;
    g_P[idx] = exp2f(a_coef * S);
}

// ============================================================
// Kernel 4b: fixup — sequential prefix over CH chunks per (b,d,n)
// ============================================================
__global__ void __launch_bounds__(256) fix_kernel() {
    const int i = blockIdx.x * 256 + threadIdx.x;    // 0..32767
    const size_t base = (size_t)i * CH;
    float h = 0.f;
#pragma unroll
    for (int q = 0; q < CH / 4; ++q) {
        float4 H = *(float4*)&g_H[base + q * 4];
        float4 P = *(float4*)&g_P[base + q * 4];
        float4 o;
        o.x = h; h = fmaf(P.x, h, H.x);
        o.y = h; h = fmaf(P.y, h, H.y);
        o.z = h; h = fmaf(P.z, h, H.z);
        o.w = h; h = fmaf(P.w, h, H.w);
        *(float4*)&g_h0[base + q * 4] = o;
    }
}

// ============================================================
// Kernel 4c: scan pass B — full recurrence from h0, smem-staged B/C,
// smem y buffer, fused residual + transposed write-out.
// ============================================================
__global__ void __launch_bounds__(256, 1) scanB_kernel(const float* __restrict__ A_log,
                                                       const float* __restrict__ x,
                                                       const float* __restrict__ Dp,
                                                       float* __restrict__ out) {
    __shared__ float s_B[CL * 17];
    __shared__ float s_C[CL * 17];
    __shared__ float s_y[CL * 17];
    __shared__ float s_dp[16];

    const int bx  = blockIdx.x;
    const int ch  = bx & (CH - 1);
    const int rest = bx >> 4;
    const int b   = rest >> 6;
    const int d0  = (rest & 63) << 4;
    const int tid = threadIdx.x;
    const int w   = tid >> 5;
    const int lane = tid & 31;
    const int half = lane >> 4;
    const int n    = lane & 15;
    const int d    = d0 + 2 * w + half;
    const int ddloc = 2 * w + half;

    const size_t off = (size_t)b * SEQ + ch * CL;
#pragma unroll
    for (int q = 0; q < (CL * NST) / 256; ++q) {
        const int idx = q * 256 + tid;
        const int t  = idx & (CL - 1);
        const int nn = idx >> 7;
        s_B[t * 17 + nn] = g_BT[(size_t)nn * TOK + off + t];
        s_C[t * 17 + nn] = g_CT[(size_t)nn * TOK + off + t];
    }
    if (tid < 16) s_dp[tid] = Dp[d0 + tid];
    __syncthreads();

    const float a_coef = -expf(A_log[d * NST + n]) * 1.44269504088896341f;
    const float* dtp = g_dtT + (size_t)d * TOK + off;
    const float* xnp = g_xnT + (size_t)d * TOK + off;

    float h = g_h0[(((size_t)b * DIM + d) * NST + n) * CH + ch];
    const int jsel = lane & 7;
    const bool doStore = !(lane & 8);

#pragma unroll 1
    for (int l = 0; l < CL; l += 8) {
        const float4 dt0 = *(const float4*)(dtp + l);
        const float4 dt1 = *(const float4*)(dtp + l + 4);
        const float4 x0  = *(const float4*)(xnp + l);
        const float4 x1  = *(const float4*)(xnp + l + 4);

        float p0, p1, p2, p3, p4, p5, p6, p7;
#define SSTEP(j, dtv, xv, pj)                               \
        {                                                   \
            const float Bv = s_B[(l + j) * 17 + n];         \
            const float Cv = s_C[(l + j) * 17 + n];         \
            const float a_ = exp2f((dtv) * a_coef);         \
            h = fmaf(a_, h, (dtv) * Bv * (xv));             \
            pj = Cv * h;                                    \
        }
        SSTEP(0, dt0.x, x0.x, p0)
        SSTEP(1, dt0.y, x0.y, p1)
        SSTEP(2, dt0.z, x0.z, p2)
        SSTEP(3, dt0.w, x0.w, p3)
        SSTEP(4, dt1.x, x1.x, p4)
        SSTEP(5, dt1.y, x1.y, p5)
        SSTEP(6, dt1.z, x1.z, p6)
        SSTEP(7, dt1.w, x1.w, p7)
#undef SSTEP

#define RED(m)                                              \
        p0 += __shfl_xor_sync(0xffffffffu, p0, m);          \
        p1 += __shfl_xor_sync(0xffffffffu, p1, m);          \
        p2 += __shfl_xor_sync(0xffffffffu, p2, m);          \
        p3 += __shfl_xor_sync(0xffffffffu, p3, m);          \
        p4 += __shfl_xor_sync(0xffffffffu, p4, m);          \
        p5 += __shfl_xor_sync(0xffffffffu, p5, m);          \
        p6 += __shfl_xor_sync(0xffffffffu, p6, m);          \
        p7 += __shfl_xor_sync(0xffffffffu, p7, m);
        RED(1) RED(2) RED(4) RED(8)
#undef RED

        float a0 = (jsel & 4) ? p4 : p0;
        float a1 = (jsel & 4) ? p5 : p1;
        float a2 = (jsel & 4) ? p6 : p2;
        float a3 = (jsel & 4) ? p7 : p3;
        float b0 = (jsel & 2) ? a2 : a0;
        float b1 = (jsel & 2) ? a3 : a1;
        float v  = (jsel & 1) ? b1 : b0;
        if (doStore) s_y[(l + jsel) * 17 + ddloc] = v;
    }
    __syncthreads();

    // write-out: 2 threads per token; out[t][d0..d0+16) = y + Dp*x
    {
        const int t  = tid >> 1;
        const int hb = (tid & 1) * 8;
        const size_t gt = off + t;
        const float* xr = x + gt * DIM + d0 + hb;
        float*       orow = out + gt * DIM + d0 + hb;
#pragma unroll
        for (int qq = 0; qq < 2; ++qq) {
            float4 xv = *(const float4*)(xr + qq * 4);
            float4 ov;
            ov.x = fmaf(s_dp[hb + qq * 4 + 0], xv.x, s_y[t * 17 + hb + qq * 4 + 0]);
            ov.y = fmaf(s_dp[hb + qq * 4 + 1], xv.y, s_y[t * 17 + hb + qq * 4 + 1]);
            ov.z = fmaf(s_dp[hb + qq * 4 + 2], xv.z, s_y[t * 17 + hb + qq * 4 + 2]);
            ov.w = fmaf(s_dp[hb + qq * 4 + 3], xv.w, s_y[t * 17 + hb + qq * 4 + 3]);
            *(float4*)(orow + qq * 4) = ov;
        }
    }
}

// ============================================================
// launch
// ============================================================
extern "C" void kernel_launch(void* const* d_in, const int* in_sizes, int n_in,
                              void* d_out, int out_size) {
    const float* x     = (const float*)d_in[0];
    const float* W_dt  = (const float*)d_in[1];
    const float* b_dt  = (const float*)d_in[2];
    const float* W_B   = (const float*)d_in[3];
    const float* W_C   = (const float*)d_in[4];
    const float* Dp    = (const float*)d_in[5];
    const float* A_log = (const float*)d_in[6];
    const float* gamma = (const float*)d_in[7];
    const float* beta  = (const float*)d_in[8];
    float* out = (float*)d_out;

    cudaFuncSetAttribute(gemm_kernel,
                         cudaFuncAttributeMaxDynamicSharedMemorySize, GEMM_SMEM);

    ln_kernel<<<TOK, 256>>>(x, gamma, beta);
    wpack_kernel<<<NPAD, 256>>>(W_dt, W_B, W_C);
    xpose_kernel<<<dim3(TOK / 32, DIM / 32), 256>>>();
    dim3 gg(TOK / 256, NPAD / 128);  // 16 x 9
    gemm_kernel<<<gg, 256, GEMM_SMEM>>>(b_dt);
    scanA_kernel<<<BSZ * 64 * CH, 256>>>(A_log);
    fix_kernel<<<(BSZ * DIM * NST) / 256, 256>>>();
    scanB_kernel<<<BSZ * 64 * CH, 256>>>(A_log, x, Dp, out);
}

// round 9
// speedup vs baseline: 1.1705x; 1.1705x over previous
#include <cuda_runtime.h>
#include <cuda_bf16.h>
#include <cstdint>

// ---------------- problem constants ----------------
#define BSZ 2
#define SEQ 2048
#define DIM 1024
#define NST 16
#define TOK (BSZ * SEQ)      // 4096 tokens
#define KPHY 2048            // physical K: [hi | lo]
#define NPAD 1152            // 1056 cols (dt 1024 + B 16 + C 16) padded
#define CH 16                // scan chunks
#define CL 128               // chunk length = SEQ/CH

// ---------------- scratch (device globals; no allocs allowed) ----------------
__device__ __nv_bfloat16 g_Abig[(size_t)TOK * KPHY];   // [t][k] hi|lo  16 MB
__device__ __nv_bfloat16 g_Bbig[(size_t)NPAD * KPHY];  // [n][k] hi|lo  4.5 MB
__device__ float g_xn [(size_t)TOK * DIM];             // layernormed x, [t][d]
__device__ float g_xnT[(size_t)DIM * TOK];             // xn transposed [d][t]
__device__ float g_dtT[(size_t)DIM * TOK];             // softplus(dt), [d][t]
__device__ float g_BT [(size_t)NST * TOK];             // B_in^T [n][t]
__device__ float g_CT [(size_t)NST * TOK];             // C_in^T [n][t]
__device__ float g_H [(size_t)BSZ * DIM * NST * CH];   // per-chunk zero-init final h
__device__ float g_P [(size_t)BSZ * DIM * NST * CH];   // per-chunk total decay
__device__ float g_h0[(size_t)BSZ * DIM * NST * CH];   // per-chunk initial state

// ---------------- helpers ----------------
__device__ __forceinline__ uint32_t smem_u32(const void* p) {
    uint32_t a;
    asm("{ .reg .u64 t; cvta.to.shared.u64 t, %1; cvt.u32.u64 %0, t; }"
        : "=r"(a) : "l"(p));
    return a;
}
__device__ __forceinline__ void cp_async16(uint32_t s, const void* g) {
    asm volatile("cp.async.cg.shared.global [%0], [%1], 16;"
                 :: "r"(s), "l"(__cvta_generic_to_global(g)) : "memory");
}
__device__ __forceinline__ void cp_commit() {
    asm volatile("cp.async.commit_group;" ::: "memory");
}
template <int N>
__device__ __forceinline__ void cp_wait() {
    asm volatile("cp.async.wait_group %0;" :: "n"(N) : "memory");
}
__device__ __forceinline__ void ldsm_x4(uint32_t& r0, uint32_t& r1,
                                        uint32_t& r2, uint32_t& r3, uint32_t a) {
    asm volatile("ldmatrix.sync.aligned.m8n8.x4.shared.b16 {%0,%1,%2,%3}, [%4];"
                 : "=r"(r0), "=r"(r1), "=r"(r2), "=r"(r3) : "r"(a));
}
__device__ __forceinline__ void mma16816(float* c, const uint32_t* a,
                                         const uint32_t* b) {
    asm volatile(
        "mma.sync.aligned.m16n8k16.row.col.f32.bf16.bf16.f32 "
        "{%0,%1,%2,%3}, {%4,%5,%6,%7}, {%8,%9}, {%0,%1,%2,%3};"
        : "+f"(c[0]), "+f"(c[1]), "+f"(c[2]), "+f"(c[3])
        : "r"(a[0]), "r"(a[1]), "r"(a[2]), "r"(a[3]), "r"(b[0]), "r"(b[1]));
}

// ============================================================
// Kernel 1: LayerNorm + bf16 hi/lo split pack into A = [hi | lo]
// ============================================================
__global__ void __launch_bounds__(256) ln_kernel(const float* __restrict__ x,
                                                 const float* __restrict__ gamma,
                                                 const float* __restrict__ beta) {
    const int t = blockIdx.x;
    const int tid = threadIdx.x;
    float4 v = ((const float4*)(x + (size_t)t * DIM))[tid];
    float s  = v.x + v.y + v.z + v.w;
    float ss = v.x * v.x + v.y * v.y + v.z * v.z + v.w * v.w;
#pragma unroll
    for (int o = 16; o; o >>= 1) {
        s  += __shfl_xor_sync(0xffffffffu, s,  o);
        ss += __shfl_xor_sync(0xffffffffu, ss, o);
    }
    __shared__ float red[16];
    const int w = tid >> 5, lane = tid & 31;
    if (lane == 0) { red[w] = s; red[8 + w] = ss; }
    __syncthreads();
    if (tid == 0) {
        float a = 0.f, b2 = 0.f;
#pragma unroll
        for (int i = 0; i < 8; ++i) { a += red[i]; b2 += red[8 + i]; }
        red[0] = a; red[8] = b2;
    }
    __syncthreads();
    const float mu  = red[0] * (1.f / DIM);
    const float var = red[8] * (1.f / DIM) - mu * mu;
    const float rs  = rsqrtf(var + 1e-5f);
    float4 g  = ((const float4*)gamma)[tid];
    float4 bb = ((const float4*)beta)[tid];
    float4 xn;
    xn.x = (v.x - mu) * rs * g.x + bb.x;
    xn.y = (v.y - mu) * rs * g.y + bb.y;
    xn.z = (v.z - mu) * rs * g.z + bb.z;
    xn.w = (v.w - mu) * rs * g.w + bb.w;
    ((float4*)(g_xn + (size_t)t * DIM))[tid] = xn;

    __nv_bfloat16 h0 = __float2bfloat16(xn.x);
    __nv_bfloat16 h1 = __float2bfloat16(xn.y);
    __nv_bfloat16 h2 = __float2bfloat16(xn.z);
    __nv_bfloat16 h3 = __float2bfloat16(xn.w);
    __nv_bfloat16 l0 = __float2bfloat16(xn.x - __bfloat162float(h0));
    __nv_bfloat16 l1 = __float2bfloat16(xn.y - __bfloat162float(h1));
    __nv_bfloat16 l2 = __float2bfloat16(xn.z - __bfloat162float(h2));
    __nv_bfloat16 l3 = __float2bfloat16(xn.w - __bfloat162float(h3));

    __nv_bfloat16* base = g_Abig + (size_t)t * KPHY + tid * 4;
    ((__nv_bfloat162*)(base))[0]        = __halves2bfloat162(h0, h1);
    ((__nv_bfloat162*)(base))[1]        = __halves2bfloat162(h2, h3);
    ((__nv_bfloat162*)(base + 1024))[0] = __halves2bfloat162(l0, l1);
    ((__nv_bfloat162*)(base + 1024))[1] = __halves2bfloat162(l2, l3);
}

// ============================================================
// Kernel 2: pack weights B = [hi | lo]
// ============================================================
__global__ void __launch_bounds__(256) wpack_kernel(const float* __restrict__ W_dt,
                                                    const float* __restrict__ W_B,
                                                    const float* __restrict__ W_C) {
    const int r = blockIdx.x;
    const float* wrow = nullptr;
    if (r < 1024)       wrow = W_dt + (size_t)r * DIM;
    else if (r < 1040)  wrow = W_B  + (size_t)(r - 1024) * DIM;
    else if (r < 1056)  wrow = W_C  + (size_t)(r - 1040) * DIM;
    for (int k = threadIdx.x; k < KPHY; k += 256) {
        float wv = 0.f;
        const int kk  = k & 1023;
        const int blk = k >> 10;
        if (wrow) wv = wrow[kk];
        __nv_bfloat16 hi = __float2bfloat16(wv);
        __nv_bfloat16 outv = blk
            ? __float2bfloat16(wv - __bfloat162float(hi)) : hi;
        g_Bbig[(size_t)r * KPHY + k] = outv;
    }
}

// ============================================================
// Kernel 2b: xn transpose  [t][d] -> [d][t]
// ============================================================
__global__ void __launch_bounds__(256) xpose_kernel() {
    __shared__ float s[32][33];
    const int t0 = blockIdx.x * 32;
    const int d0 = blockIdx.y * 32;
    const int tx = threadIdx.x & 31;
    const int ty = threadIdx.x >> 5;
#pragma unroll
    for (int i = 0; i < 4; ++i)
        s[ty + i * 8][tx] = g_xn[(size_t)(t0 + ty + i * 8) * DIM + d0 + tx];
    __syncthreads();
#pragma unroll
    for (int i = 0; i < 4; ++i)
        g_xnT[(size_t)(d0 + ty + i * 8) * TOK + t0 + tx] = s[tx][ty + i * 8];
}

// ============================================================
// Kernel 3: bf16 mma.sync GEMM, CTA tile 128x128.
// Iterate 32 PHYSICAL k-chunks; each iteration loads {A_hi,A_lo,B_hi,B_lo}
// (40KB) once and computes the 3 compensation products from registers:
//   acc += A_hi*B_hi + A_hi*B_lo + A_lo*B_hi
// 2-stage double buffer (80KB smem, 2 CTAs/SM), 2 syncs per 3 chunk-equivs.
// ============================================================
#define BK 32
#define SROW 40                  // padded smem row stride in bf16 elems (80 B)
#define BUFB 10240u              // one 128x32 tile
#define STAGE_BYTES 40960u       // A_hi A_lo B_hi B_lo
#define GEMM_SMEM 81920

__global__ void __launch_bounds__(256) gemm_kernel(const float* __restrict__ b_dt) {
    extern __shared__ char smem_raw[];

    const int tid  = threadIdx.x;
    const int wid  = tid >> 5;
    const int lane = tid & 31;
    const int mt = blockIdx.x;    // 0..31
    const int nt = blockIdx.y;    // 0..8
    const int warp_m = wid & 3;
    const int warp_n = wid >> 2;
    const int m0 = warp_m * 32;
    const int n0 = warp_n * 64;

    const __nv_bfloat16* Ag = g_Abig + (size_t)mt * 128 * KPHY;
    const __nv_bfloat16* Bg = g_Bbig + (size_t)nt * 128 * KPHY;

    const uint32_t sbase = smem_u32(smem_raw);

    const int id0 = tid * 2;
    auto load_phys = [&](int pc, int stage) {
        const int k0 = pc * 32;
        const uint32_t s0 = sbase + (uint32_t)stage * STAGE_BYTES;
#pragma unroll
        for (int r = 0; r < 2; ++r) {
            const int id  = id0 + r;           // 0..511
            const int row = id >> 2;
            const int ch  = id & 3;
            const uint32_t soff = (uint32_t)(row * SROW + ch * 8) * 2;
            const __nv_bfloat16* gA = Ag + (size_t)row * KPHY + k0 + ch * 8;
            const __nv_bfloat16* gB = Bg + (size_t)row * KPHY + k0 + ch * 8;
            cp_async16(s0 +             soff, gA);          // A_hi
            cp_async16(s0 + BUFB +      soff, gA + 1024);   // A_lo
            cp_async16(s0 + 2u * BUFB + soff, gB);          // B_hi
            cp_async16(s0 + 3u * BUFB + soff, gB + 1024);   // B_lo
        }
        cp_commit();
    };

    float acc[2][8][4];
#pragma unroll
    for (int mf = 0; mf < 2; ++mf)
#pragma unroll
        for (int nf = 0; nf < 8; ++nf)
#pragma unroll
            for (int i = 0; i < 4; ++i) acc[mf][nf][i] = 0.f;

    load_phys(0, 0);

    for (int pc = 0; pc < 32; ++pc) {
        const int buf = pc & 1;
        if (pc + 1 < 32) { load_phys(pc + 1, buf ^ 1); cp_wait<1>(); }
        else             { cp_wait<0>(); }
        __syncthreads();

        const uint32_t sah = sbase + (uint32_t)buf * STAGE_BYTES;
        const uint32_t sal = sah + BUFB;
        const uint32_t sbh = sah + 2u * BUFB;
        const uint32_t sbl = sah + 3u * BUFB;

#pragma unroll
        for (int kk = 0; kk < BK; kk += 16) {
            const uint32_t arow_off =
                (uint32_t)((m0 + (lane & 15)) * SROW + kk + ((lane >> 4) << 3)) * 2;
            uint32_t ah[2][4], al[2][4];
#pragma unroll
            for (int mf = 0; mf < 2; ++mf) {
                const uint32_t aoff = arow_off + (uint32_t)(mf * 16 * SROW) * 2;
                ldsm_x4(ah[mf][0], ah[mf][1], ah[mf][2], ah[mf][3], sah + aoff);
                ldsm_x4(al[mf][0], al[mf][1], al[mf][2], al[mf][3], sal + aoff);
            }
            uint32_t bh[8][2], bl[8][2];
#pragma unroll
            for (int g = 0; g < 4; ++g) {
                const int nrow = n0 + g * 16 + ((lane >> 4) << 3) + (lane & 7);
                const int kcol = kk + (((lane >> 3) & 1) << 3);
                const uint32_t boff = (uint32_t)(nrow * SROW + kcol) * 2;
                uint32_t r0, r1, r2, r3;
                ldsm_x4(r0, r1, r2, r3, sbh + boff);
                bh[g * 2][0] = r0; bh[g * 2][1] = r1;
                bh[g * 2 + 1][0] = r2; bh[g * 2 + 1][1] = r3;
                ldsm_x4(r0, r1, r2, r3, sbl + boff);
                bl[g * 2][0] = r0; bl[g * 2][1] = r1;
                bl[g * 2 + 1][0] = r2; bl[g * 2 + 1][1] = r3;
            }
#pragma unroll
            for (int mf = 0; mf < 2; ++mf)
#pragma unroll
                for (int nf = 0; nf < 8; ++nf) {
                    mma16816(acc[mf][nf], ah[mf], bh[nf]);
                    mma16816(acc[mf][nf], ah[mf], bl[nf]);
                    mma16816(acc[mf][nf], al[mf], bh[nf]);
                }
        }
        __syncthreads();
    }

    // ---------------- epilogue: smem transpose, coalesced stores ----------------
    float* tb = (float*)smem_raw;                 // [64 cols][132 tokens]
    const int trow  = lane >> 2;
    const int cpair = (lane & 3) * 2;
    const int r   = tid >> 2;
    const int seg = tid & 3;

#pragma unroll 1
    for (int h = 0; h < 2; ++h) {
        __syncthreads();
        if (warp_n == h) {
#pragma unroll
            for (int mf = 0; mf < 2; ++mf)
#pragma unroll
                for (int nf = 0; nf < 8; ++nf)
#pragma unroll
                    for (int i = 0; i < 4; ++i) {
                        const int tok_l = m0 + mf * 16 + trow + 8 * (i >> 1);
                        const int col_l = nf * 8 + cpair + (i & 1);
                        tb[col_l * 132 + tok_l] = acc[mf][nf][i];
                    }
        }
        __syncthreads();
        if (nt < 8) {
            const int dd = nt * 128 + h * 64 + r;
            const float bias = b_dt[dd];
            float* dst = g_dtT + (size_t)dd * TOK + mt * 128;
#pragma unroll
            for (int q = 0; q < 8; ++q) {
                const int tl = seg * 32 + q * 4;
                float4 v = *(float4*)&tb[r * 132 + tl];
                float4 o;
                float u;
                u = v.x + bias; o.x = (u > 20.f) ? u : log1pf(expf(u));
                u = v.y + bias; o.y = (u > 20.f) ? u : log1pf(expf(u));
                u = v.z + bias; o.z = (u > 20.f) ? u : log1pf(expf(u));
                u = v.w + bias; o.w = (u > 20.f) ? u : log1pf(expf(u));
                *(float4*)&dst[tl] = o;
            }
        } else {
            const int cc = h * 64 + r;
            if (cc < 32) {
                float* dst = (cc < 16 ? g_BT + (size_t)cc * TOK
                                      : g_CT + (size_t)(cc - 16) * TOK) + mt * 128;
#pragma unroll
                for (int q = 0; q < 8; ++q) {
                    const int tl = seg * 32 + q * 4;
                    *(float4*)&dst[tl] = *(float4*)&tb[r * 132 + tl];
                }
            }
        }
    }
}

// ============================================================
// Kernel 4a: scan pass A — per-chunk zero-init final state H + decay P.
// ============================================================
__global__ void __launch_bounds__(256, 1) scanA_kernel(const float* __restrict__ A_log) {
    __shared__ float s_B[CL * 17];
    const int bx  = blockIdx.x;
    const int ch  = bx & (CH - 1);
    const int rest = bx >> 4;
    const int b   = rest >> 6;
    const int d0  = (rest & 63) << 4;
    const int tid = threadIdx.x;
    const int w   = tid >> 5;
    const int lane = tid & 31;
    const int half = lane >> 4;
    const int n    = lane & 15;
    const int d    = d0 + 2 * w + half;

    const size_t off = (size_t)b * SEQ + ch * CL;
#pragma unroll
    for (int q = 0; q < (CL * NST) / 256; ++q) {
        const int idx = q * 256 + tid;
        const int t  = idx & (CL - 1);
        const int nn = idx >> 7;
        s_B[t * 17 + nn] = g_BT[(size_t)nn * TOK + off + t];
    }
    __syncthreads();

    const float a_coef = -expf(A_log[d * NST + n]) * 1.44269504088896341f;
    const float* dtp = g_dtT + (size_t)d * TOK + off;
    const float* xnp = g_xnT + (size_t)d * TOK + off;

    float h = 0.f, S = 0.f;
#pragma unroll 1
    for (int l = 0; l < CL; l += 8) {
        const float4 dt0 = *(const float4*)(dtp + l);
        const float4 dt1 = *(const float4*)(dtp + l + 4);
        const float4 x0  = *(const float4*)(xnp + l);
        const float4 x1  = *(const float4*)(xnp + l + 4);
#define ASTEP(j, dtv, xv)                                   \
        {                                                   \
            const float Bv = s_B[(l + j) * 17 + n];         \
            const float a_ = exp2f((dtv) * a_coef);         \
            h = fmaf(a_, h, (dtv) * Bv * (xv));             \
            S += (dtv);                                     \
        }
        ASTEP(0, dt0.x, x0.x) ASTEP(1, dt0.y, x0.y)
        ASTEP(2, dt0.z, x0.z) ASTEP(3, dt0.w, x0.w)
        ASTEP(4, dt1.x, x1.x) ASTEP(5, dt1.y, x1.y)
        ASTEP(6, dt1.z, x1.z) ASTEP(7, dt1.w, x1.w)
#undef ASTEP
    }
    const size_t idx = (((size_t)b * DIM + d) * NST + n) * CH + ch;
    g_H[idx] = h;
    g_P[idx] = exp2f(a_coef * S);
}

// ============================================================
// Kernel 4b: fixup — sequential prefix over CH chunks per (b,d,n)
// ============================================================
__global__ void __launch_bounds__(256) fix_kernel() {
    const int i = blockIdx.x * 256 + threadIdx.x;    // 0..32767
    const size_t base = (size_t)i * CH;
    float h = 0.f;
#pragma unroll
    for (int q = 0; q < CH / 4; ++q) {
        float4 H = *(float4*)&g_H[base + q * 4];
        float4 P = *(float4*)&g_P[base + q * 4];
        float4 o;
        o.x = h; h = fmaf(P.x, h, H.x);
        o.y = h; h = fmaf(P.y, h, H.y);
        o.z = h; h = fmaf(P.z, h, H.z);
        o.w = h; h = fmaf(P.w, h, H.w);
        *(float4*)&g_h0[base + q * 4] = o;
    }
}

// ============================================================
// Kernel 4c: scan pass B — full recurrence from h0, smem-staged B/C,
// smem y buffer, fused residual + transposed write-out.
// ============================================================
__global__ void __launch_bounds__(256, 1) scanB_kernel(const float* __restrict__ A_log,
                                                       const float* __restrict__ x,
                                                       const float* __restrict__ Dp,
                                                       float* __restrict__ out) {
    __shared__ float s_B[CL * 17];
    __shared__ float s_C[CL * 17];
    __shared__ float s_y[CL * 17];
    __shared__ float s_dp[16];

    const int bx  = blockIdx.x;
    const int ch  = bx & (CH - 1);
    const int rest = bx >> 4;
    const int b   = rest >> 6;
    const int d0  = (rest & 63) << 4;
    const int tid = threadIdx.x;
    const int w   = tid >> 5;
    const int lane = tid & 31;
    const int half = lane >> 4;
    const int n    = lane & 15;
    const int d    = d0 + 2 * w + half;
    const int ddloc = 2 * w + half;

    const size_t off = (size_t)b * SEQ + ch * CL;
#pragma unroll
    for (int q = 0; q < (CL * NST) / 256; ++q) {
        const int idx = q * 256 + tid;
        const int t  = idx & (CL - 1);
        const int nn = idx >> 7;
        s_B[t * 17 + nn] = g_BT[(size_t)nn * TOK + off + t];
        s_C[t * 17 + nn] = g_CT[(size_t)nn * TOK + off + t];
    }
    if (tid < 16) s_dp[tid] = Dp[d0 + tid];
    __syncthreads();

    const float a_coef = -expf(A_log[d * NST + n]) * 1.44269504088896341f;
    const float* dtp = g_dtT + (size_t)d * TOK + off;
    const float* xnp = g_xnT + (size_t)d * TOK + off;

    float h = g_h0[(((size_t)b * DIM + d) * NST + n) * CH + ch];
    const int jsel = lane & 7;
    const bool doStore = !(lane & 8);

#pragma unroll 1
    for (int l = 0; l < CL; l += 8) {
        const float4 dt0 = *(const float4*)(dtp + l);
        const float4 dt1 = *(const float4*)(dtp + l + 4);
        const float4 x0  = *(const float4*)(xnp + l);
        const float4 x1  = *(const float4*)(xnp + l + 4);

        float p0, p1, p2, p3, p4, p5, p6, p7;
#define SSTEP(j, dtv, xv, pj)                               \
        {                                                   \
            const float Bv = s_B[(l + j) * 17 + n];         \
            const float Cv = s_C[(l + j) * 17 + n];         \
            const float a_ = exp2f((dtv) * a_coef);         \
            h = fmaf(a_, h, (dtv) * Bv * (xv));             \
            pj = Cv * h;                                    \
        }
        SSTEP(0, dt0.x, x0.x, p0)
        SSTEP(1, dt0.y, x0.y, p1)
        SSTEP(2, dt0.z, x0.z, p2)
        SSTEP(3, dt0.w, x0.w, p3)
        SSTEP(4, dt1.x, x1.x, p4)
        SSTEP(5, dt1.y, x1.y, p5)
        SSTEP(6, dt1.z, x1.z, p6)
        SSTEP(7, dt1.w, x1.w, p7)
#undef SSTEP

#define RED(m)                                              \
        p0 += __shfl_xor_sync(0xffffffffu, p0, m);          \
        p1 += __shfl_xor_sync(0xffffffffu, p1, m);          \
        p2 += __shfl_xor_sync(0xffffffffu, p2, m);          \
        p3 += __shfl_xor_sync(0xffffffffu, p3, m);          \
        p4 += __shfl_xor_sync(0xffffffffu, p4, m);          \
        p5 += __shfl_xor_sync(0xffffffffu, p5, m);          \
        p6 += __shfl_xor_sync(0xffffffffu, p6, m);          \
        p7 += __shfl_xor_sync(0xffffffffu, p7, m);
        RED(1) RED(2) RED(4) RED(8)
#undef RED

        float a0 = (jsel & 4) ? p4 : p0;
        float a1 = (jsel & 4) ? p5 : p1;
        float a2 = (jsel & 4) ? p6 : p2;
        float a3 = (jsel & 4) ? p7 : p3;
        float b0 = (jsel & 2) ? a2 : a0;
        float b1 = (jsel & 2) ? a3 : a1;
        float v  = (jsel & 1) ? b1 : b0;
        if (doStore) s_y[(l + jsel) * 17 + ddloc] = v;
    }
    __syncthreads();

    // write-out: 2 threads per token; out[t][d0..d0+16) = y + Dp*x
    {
        const int t  = tid >> 1;
        const int hb = (tid & 1) * 8;
        const size_t gt = off + t;
        const float* xr = x + gt * DIM + d0 + hb;
        float*       orow = out + gt * DIM + d0 + hb;
#pragma unroll
        for (int qq = 0; qq < 2; ++qq) {
            float4 xv = *(const float4*)(xr + qq * 4);
            float4 ov;
            ov.x = fmaf(s_dp[hb + qq * 4 + 0], xv.x, s_y[t * 17 + hb + qq * 4 + 0]);
            ov.y = fmaf(s_dp[hb + qq * 4 + 1], xv.y, s_y[t * 17 + hb + qq * 4 + 1]);
            ov.z = fmaf(s_dp[hb + qq * 4 + 2], xv.z, s_y[t * 17 + hb + qq * 4 + 2]);
            ov.w = fmaf(s_dp[hb + qq * 4 + 3], xv.w, s_y[t * 17 + hb + qq * 4 + 3]);
            *(float4*)(orow + qq * 4) = ov;
        }
    }
}

// ============================================================
// launch
// ============================================================
extern "C" void kernel_launch(void* const* d_in, const int* in_sizes, int n_in,
                              void* d_out, int out_size) {
    const float* x     = (const float*)d_in[0];
    const float* W_dt  = (const float*)d_in[1];
    const float* b_dt  = (const float*)d_in[2];
    const float* W_B   = (const float*)d_in[3];
    const float* W_C   = (const float*)d_in[4];
    const float* Dp    = (const float*)d_in[5];
    const float* A_log = (const float*)d_in[6];
    const float* gamma = (const float*)d_in[7];
    const float* beta  = (const float*)d_in[8];
    float* out = (float*)d_out;

    cudaFuncSetAttribute(gemm_kernel,
                         cudaFuncAttributeMaxDynamicSharedMemorySize, GEMM_SMEM);

    ln_kernel<<<TOK, 256>>>(x, gamma, beta);
    wpack_kernel<<<NPAD, 256>>>(W_dt, W_B, W_C);
    xpose_kernel<<<dim3(TOK / 32, DIM / 32), 256>>>();
    dim3 gg(TOK / 128, NPAD / 128);  // 32 x 9
    gemm_kernel<<<gg, 256, GEMM_SMEM>>>(b_dt);
    scanA_kernel<<<BSZ * 64 * CH, 256>>>(A_log);
    fix_kernel<<<(BSZ * DIM * NST) / 256, 256>>>();
    scanB_kernel<<<BSZ * 64 * CH, 256>>>(A_log, x, Dp, out);
}